// round 16
// baseline (speedup 1.0000x reference)
#include <cuda_runtime.h>
#include <cuda_fp16.h>
#include <math.h>
#include <stdint.h>

#define BATCH 16384
#define DIM   512
#define HID   2048

#define BM 128
#define BN 128
#define BK 64
#define THREADS 128

// smem: 128B rows (64 fp16), XOR-swizzled 16B chunks (chunk ^= row&7)
#define OA_H   0
#define OB_H   16384
#define STAGE  32768
#define NSTAGE 3
#define SMEM_TOTAL (NSTAGE * STAGE)   // 98304/CTA -> 2 CTAs/SM

// ---------------- scratch (allocation-free) ----------------
__device__ __half g_zh[(size_t)BATCH * DIM];
__device__ __half g_h1h[(size_t)BATCH * HID];
__device__ __half g_h2h[(size_t)BATCH * HID];
__device__ __half g_d2h[(size_t)BATCH * HID];
__device__ __half g_d1h[(size_t)BATCH * HID];
__device__ float g_v3[HID];
__device__ __half g_W1h[HID * DIM];
__device__ __half g_W2h[HID * HID];
__device__ __half g_W3h[DIM * HID];
__device__ __half g_W2Th[HID * HID];
__device__ __half g_W1Th[DIM * HID];

enum { EPI_H1 = 0, EPI_H2D2 = 1, EPI_G34 = 2, EPI_GT = 3 };

// ---------------- helpers ----------------
__device__ __forceinline__ uint32_t s2u(const void* p) {
    uint32_t a;
    asm("{ .reg .u64 t; cvta.to.shared.u64 t, %1; cvt.u32.u64 %0, t; }" : "=r"(a) : "l"(p));
    return a;
}

// swizzled byte offset within a ROWSx64 fp16 tile: 128B rows, chunk ^= row&7
__device__ __forceinline__ uint32_t swoff(int row, int seg) {
    return (uint32_t)(row * 128 + ((seg ^ (row & 7)) << 4));
}

__device__ __forceinline__ void ldsm4(uint32_t* r, uint32_t addr) {
    asm volatile("ldmatrix.sync.aligned.m8n8.x4.shared.b16 {%0,%1,%2,%3}, [%4];"
                 : "=r"(r[0]), "=r"(r[1]), "=r"(r[2]), "=r"(r[3]) : "r"(addr));
}

__device__ __forceinline__ void mma16816(float* c, const uint32_t* a, const uint32_t* b) {
    asm volatile("mma.sync.aligned.m16n8k16.row.col.f32.f16.f16.f32 "
                 "{%0,%1,%2,%3}, {%4,%5,%6,%7}, {%8,%9}, {%0,%1,%2,%3};"
                 : "+f"(c[0]), "+f"(c[1]), "+f"(c[2]), "+f"(c[3])
                 : "r"(a[0]), "r"(a[1]), "r"(a[2]), "r"(a[3]), "r"(b[0]), "r"(b[1]));
}

__device__ __forceinline__ void cp16(uint32_t dst, const void* src) {
    asm volatile("cp.async.cg.shared.global [%0], [%1], 16;" :: "r"(dst), "l"(src) : "memory");
}

__device__ __forceinline__ float ftanh(float x) {
    float e = __expf(2.f * x);
    return 1.f - __fdividef(2.f, e + 1.f);
}

// one tile plane: 128 rows x 64 cols fp16 via cp.async into swizzled smem (128 threads)
__device__ __forceinline__ void cpPlane(uint32_t dst, const __half* __restrict__ src,
                                        int ld, int r0, int k0, int tid) {
#pragma unroll
    for (int i = 0; i < 8; ++i) {
        int idx = tid + i * 128;
        int row = idx >> 3, seg = idx & 7;
        cp16(dst + swoff(row, seg), src + (size_t)(r0 + row) * ld + k0 + seg * 8);
    }
}

// ---------------- fp16 warp-MMA GEMM: 128x128 tile, 4 warps of 64x64, BK=64 ----------------
// 3-stage smem pipeline + double-buffered register fragments (ldsm ks+1 ahead of MMA ks)
template <int EPI>
__global__ void __launch_bounds__(THREADS, 2) mma_gemm(
    const __half* __restrict__ Ah, const __half* __restrict__ A2,
    const __half* __restrict__ Bh, const __half* __restrict__ B2,
    const float* __restrict__ bias, const float* __restrict__ v3p,
    float* __restrict__ C, int ldc,
    __half* __restrict__ P1, __half* __restrict__ P2,
    const __half* __restrict__ Xh, const float* __restrict__ eps,
    int K, int ldp)
{
    extern __shared__ char smem[];
    const uint32_t sb = s2u(smem);
    const int tid = threadIdx.x, lane = tid & 31, wid = tid >> 5;
    const int wm = wid >> 1, wn = wid & 1;           // 2x2 warps, 64x64 each
    const int m0 = blockIdx.y * BM, n0 = blockIdx.x * BN;
    const int NC = K >> 6;                            // 64-wide chunks

    // G34: n-tile selects operand set + epilogue flavor (uniform per CTA)
    bool isOut = true;
    int nB0 = n0;
    const __half* Ap = Ah;
    const __half* Bp = Bh;
    if (EPI == EPI_G34 && n0 >= DIM) {
        isOut = false; nB0 = n0 - DIM; Ap = A2; Bp = B2;
    }

    float acc[4][8][4];
#pragma unroll
    for (int a = 0; a < 4; ++a)
#pragma unroll
        for (int b = 0; b < 8; ++b)
#pragma unroll
            for (int c = 0; c < 4; ++c) acc[a][b][c] = 0.f;

    // swizzled fragment base offsets; ks step = XOR (ks<<5)
    const int aRow = lane & 15;
    const int bRow = (lane & 7) + ((lane >> 4) << 3);
    uint32_t aBase[4], bBase[4];
#pragma unroll
    for (int mb = 0; mb < 4; ++mb)
        aBase[mb] = swoff(wm * 64 + mb * 16 + aRow, lane >> 4);
#pragma unroll
    for (int pr = 0; pr < 4; ++pr)
        bBase[pr] = swoff(wn * 64 + pr * 16 + bRow, (lane >> 3) & 1);

    // prologue: chunks 0,1 -> stages 0,1
#pragma unroll
    for (int c = 0; c < 2; ++c) {
        const uint32_t st = sb + c * STAGE;
        if (c < NC) {
            cpPlane(st + OA_H, Ap, K, m0, c * BK, tid);
            cpPlane(st + OB_H, Bp, K, nB0, c * BK, tid);
        }
        asm volatile("cp.async.commit_group;" ::: "memory");
    }

    uint32_t bf[2][4][4], af[2][4][4];   // double-buffered fragments
    int sidx = 0;
    for (int c = 0; c < NC; ++c) {
        asm volatile("cp.async.wait_group 1;" ::: "memory");  // chunk c arrived
        __syncthreads();                                      // visibility + WAR (dist-2 write)
        const uint32_t st = sb + sidx * STAGE;

        // issue ks=0 fragment loads FIRST (MMAs can start ASAP)...
#pragma unroll
        for (int pr = 0; pr < 4; ++pr) ldsm4(bf[0][pr], st + OB_H + bBase[pr]);
#pragma unroll
        for (int mb = 0; mb < 4; ++mb) ldsm4(af[0][mb], st + OA_H + aBase[mb]);

        // ...then the gmem prefetch for chunk c+2 (issue cost hides under MMAs)
        if (c + 2 < NC) {
            int s2 = sidx + 2; if (s2 >= NSTAGE) s2 -= NSTAGE;
            const uint32_t nx = sb + s2 * STAGE;
            cpPlane(nx + OA_H, Ap, K, m0, (c + 2) * BK, tid);
            cpPlane(nx + OB_H, Bp, K, nB0, (c + 2) * BK, tid);
        }
        asm volatile("cp.async.commit_group;" ::: "memory");

#pragma unroll
        for (int ks = 0; ks < 4; ++ks) {
            const int cur = ks & 1, nxt = cur ^ 1;
            if (ks < 3) {   // prefetch next ks fragments before MMAs of current
                const uint32_t kx = (ks + 1) << 5;
#pragma unroll
                for (int pr = 0; pr < 4; ++pr) ldsm4(bf[nxt][pr], st + OB_H + (bBase[pr] ^ kx));
#pragma unroll
                for (int mb = 0; mb < 4; ++mb) ldsm4(af[nxt][mb], st + OA_H + (aBase[mb] ^ kx));
            }
#pragma unroll
            for (int mb = 0; mb < 4; ++mb)
#pragma unroll
                for (int nb = 0; nb < 8; ++nb) {
                    const uint32_t* fh = &bf[cur][nb >> 1][(nb & 1) * 2];
                    mma16816(acc[mb][nb], af[cur][mb], fh);
                }
        }
        if (++sidx == NSTAGE) sidx = 0;
    }

    // ---------------- epilogue ----------------
    const int g = lane >> 2, tg = lane & 3;
#pragma unroll
    for (int mb = 0; mb < 4; ++mb) {
        float p0 = 0.f, p1 = 0.f;   // EPI_GT per-row partial traces
#pragma unroll
        for (int nb = 0; nb < 8; ++nb) {
            float* cc = acc[mb][nb];
            const int r0 = m0 + wm * 64 + mb * 16 + g;
            const int col = nB0 + wn * 64 + nb * 8 + tg * 2;
            if (EPI == EPI_H1) {
                float bx = __ldg(bias + col), by = __ldg(bias + col + 1);
                float t0 = ftanh(cc[0] + bx), t1 = ftanh(cc[1] + by);
                float t2 = ftanh(cc[2] + bx), t3 = ftanh(cc[3] + by);
                *reinterpret_cast<__half2*>(P1 + (size_t)r0 * ldp + col) =
                    __halves2half2(__float2half_rn(t0), __float2half_rn(t1));
                *reinterpret_cast<__half2*>(P1 + (size_t)(r0 + 8) * ldp + col) =
                    __halves2half2(__float2half_rn(t2), __float2half_rn(t3));
            } else if (EPI == EPI_H2D2) {
                float bx = __ldg(bias + col), by = __ldg(bias + col + 1);
                float vx = __ldg(v3p + col), vy = __ldg(v3p + col + 1);
                float t0 = ftanh(cc[0] + bx), t1 = ftanh(cc[1] + by);
                float t2 = ftanh(cc[2] + bx), t3 = ftanh(cc[3] + by);
                *reinterpret_cast<__half2*>(P1 + (size_t)r0 * ldp + col) =
                    __halves2half2(__float2half_rn(t0), __float2half_rn(t1));
                *reinterpret_cast<__half2*>(P1 + (size_t)(r0 + 8) * ldp + col) =
                    __halves2half2(__float2half_rn(t2), __float2half_rn(t3));
                *reinterpret_cast<__half2*>(P2 + (size_t)r0 * ldp + col) =
                    __halves2half2(__float2half_rn(vx * (1.f - t0 * t0)),
                                   __float2half_rn(vy * (1.f - t1 * t1)));
                *reinterpret_cast<__half2*>(P2 + (size_t)(r0 + 8) * ldp + col) =
                    __halves2half2(__float2half_rn(vx * (1.f - t2 * t2)),
                                   __float2half_rn(vy * (1.f - t3 * t3)));
            } else if (EPI == EPI_G34) {
                if (isOut) {
                    float bx = __ldg(bias + col), by = __ldg(bias + col + 1);
                    C[(size_t)r0 * ldc + col]     = cc[0] + bx;
                    C[(size_t)r0 * ldc + col + 1] = cc[1] + by;
                    C[(size_t)(r0 + 8) * ldc + col]     = cc[2] + bx;
                    C[(size_t)(r0 + 8) * ldc + col + 1] = cc[3] + by;
                } else {
#pragma unroll
                    for (int rr = 0; rr < 2; ++rr) {
                        size_t off = (size_t)(r0 + rr * 8) * ldp + col;
                        __half2 hh = *reinterpret_cast<const __half2*>(Xh + off);
                        float h0 = __half2float(hh.x), h1 = __half2float(hh.y);
                        *reinterpret_cast<__half2*>(P1 + off) = __halves2half2(
                            __float2half_rn(cc[rr * 2] * (1.f - h0 * h0)),
                            __float2half_rn(cc[rr * 2 + 1] * (1.f - h1 * h1)));
                    }
                }
            } else {  // EPI_GT: g values stay in regs; dot with 3 eps vectors
                size_t o0 = (size_t)r0 * DIM + col;
                size_t o1 = (size_t)(r0 + 8) * DIM + col;
                float2 a0 = *(const float2*)(eps + o0);
                float2 b0 = *(const float2*)(eps + (size_t)BATCH * DIM + o0);
                float2 c0 = *(const float2*)(eps + (size_t)2 * BATCH * DIM + o0);
                float2 a1 = *(const float2*)(eps + o1);
                float2 b1 = *(const float2*)(eps + (size_t)BATCH * DIM + o1);
                float2 c1 = *(const float2*)(eps + (size_t)2 * BATCH * DIM + o1);
                p0 += cc[0] * (a0.x + b0.x + c0.x) + cc[1] * (a0.y + b0.y + c0.y);
                p1 += cc[2] * (a1.x + b1.x + c1.x) + cc[3] * (a1.y + b1.y + c1.y);
            }
        }
        if (EPI == EPI_GT) {
            p0 += __shfl_xor_sync(0xFFFFFFFFu, p0, 1);
            p0 += __shfl_xor_sync(0xFFFFFFFFu, p0, 2);
            p1 += __shfl_xor_sync(0xFFFFFFFFu, p1, 1);
            p1 += __shfl_xor_sync(0xFFFFFFFFu, p1, 2);
            if (tg == 0) {
                const int r0 = m0 + wm * 64 + mb * 16 + g;
                atomicAdd(C + (size_t)r0 * (DIM + 1) + DIM, p0 * (1.f / 3.f));
                atomicAdd(C + (size_t)(r0 + 8) * (DIM + 1) + DIM, p1 * (1.f / 3.f));
            }
        }
    }
}

// ---------------- merged prep kernel ----------------
#define PB_W1   4096
#define PB_W2   (PB_W1 + 16384)
#define PB_W3   (PB_W2 + 4096)
#define PB_W1T  (PB_W3 + 1024)
#define PB_W2T  (PB_W1T + 4096)
#define PB_V3   (PB_W2T + 8)

__device__ __forceinline__ void seg_split(const float* __restrict__ W,
                                          __half* __restrict__ hi,
                                          int base, int tid) {
    int i = base * 256 + tid;
    hi[i] = __float2half_rn(W[i]);
}

__device__ __forceinline__ void seg_splitT(const float* __restrict__ in,
                                           __half* __restrict__ hi,
                                           int K, int Nn, int tileIdx, int tid) {
    __shared__ float t[32][33];
    int tilesX = K / 32;
    int k0 = (tileIdx % tilesX) * 32, n0 = (tileIdx / tilesX) * 32;
    int tx = tid & 31, ty = tid >> 5;
#pragma unroll
    for (int i = 0; i < 32; i += 8)
        t[ty + i][tx] = in[(size_t)(k0 + ty + i) * Nn + n0 + tx];
    __syncthreads();
#pragma unroll
    for (int i = 0; i < 32; i += 8)
        hi[(size_t)(n0 + ty + i) * K + k0 + tx] = __float2half_rn(t[tx][ty + i]);
}

__global__ void __launch_bounds__(256) k_prep(const float* __restrict__ W1,
                                              const float* __restrict__ W2,
                                              const float* __restrict__ W3) {
    int b = blockIdx.x, tid = threadIdx.x;
    if (b < PB_W1) {
        seg_split(W1, g_W1h, b, tid);
    } else if (b < PB_W2) {
        seg_split(W2, g_W2h, b - PB_W1, tid);
    } else if (b < PB_W3) {
        seg_split(W3, g_W3h, b - PB_W2, tid);
    } else if (b < PB_W1T) {
        seg_splitT(W1, g_W1Th, HID, DIM, b - PB_W3, tid);
    } else if (b < PB_W2T) {
        seg_splitT(W2, g_W2Th, HID, HID, b - PB_W1T, tid);
    } else {
        int j = (b - PB_W2T) * 256 + tid;
        float s = 0.f;
#pragma unroll 8
        for (int i = 0; i < DIM; ++i) s += W3[(size_t)i * HID + j];
        g_v3[j] = s;
    }
}

// pack z to fp16 AND zero the trace column of out (re-done every replay)
__global__ void k_pack_z(const float* __restrict__ aug, float* __restrict__ out) {
    int b = blockIdx.x, t = threadIdx.x;
    g_zh[(size_t)b * DIM + t] = __float2half_rn(aug[(size_t)b * (DIM + 1) + t]);
    if (t == 0) out[(size_t)b * (DIM + 1) + DIM] = 0.f;
}

// ---------------- launch ----------------
extern "C" void kernel_launch(void* const* d_in, const int* in_sizes, int n_in,
                              void* d_out, int out_size) {
    const float* aug = (const float*)d_in[1];
    const float* eps = (const float*)d_in[2];
    const float* W1  = (const float*)d_in[3];
    const float* b1  = (const float*)d_in[4];
    const float* W2  = (const float*)d_in[5];
    const float* b2  = (const float*)d_in[6];
    const float* W3  = (const float*)d_in[7];
    const float* b3  = (const float*)d_in[8];
    float* out = (float*)d_out;

    __half *zh, *h1h, *h2h, *d2h, *d1h;
    cudaGetSymbolAddress((void**)&zh,  g_zh);
    cudaGetSymbolAddress((void**)&h1h, g_h1h);
    cudaGetSymbolAddress((void**)&h2h, g_h2h);
    cudaGetSymbolAddress((void**)&d2h, g_d2h);
    cudaGetSymbolAddress((void**)&d1h, g_d1h);
    float *v3p;
    cudaGetSymbolAddress((void**)&v3p, g_v3);
    __half *w1h, *w2h, *w3h, *w2th, *w1th;
    cudaGetSymbolAddress((void**)&w1h,  g_W1h);
    cudaGetSymbolAddress((void**)&w2h,  g_W2h);
    cudaGetSymbolAddress((void**)&w3h,  g_W3h);
    cudaGetSymbolAddress((void**)&w2th, g_W2Th);
    cudaGetSymbolAddress((void**)&w1th, g_W1Th);

    cudaFuncSetAttribute(mma_gemm<EPI_H1>,   cudaFuncAttributeMaxDynamicSharedMemorySize, SMEM_TOTAL);
    cudaFuncSetAttribute(mma_gemm<EPI_H2D2>, cudaFuncAttributeMaxDynamicSharedMemorySize, SMEM_TOTAL);
    cudaFuncSetAttribute(mma_gemm<EPI_G34>,  cudaFuncAttributeMaxDynamicSharedMemorySize, SMEM_TOTAL);
    cudaFuncSetAttribute(mma_gemm<EPI_GT>,   cudaFuncAttributeMaxDynamicSharedMemorySize, SMEM_TOTAL);

    // launch 0: all weight prep in one grid
    k_prep<<<PB_V3, 256>>>(W1, W2, W3);
    // launch 1: activation pack + trace-column zero
    k_pack_z<<<BATCH, DIM>>>(aug, out);

    // launch 2 — G1: h1 = tanh(z @ W1^T + b1)   [K=512]
    mma_gemm<EPI_H1><<<dim3(HID / BN, BATCH / BM), THREADS, SMEM_TOTAL>>>(
        zh, nullptr, w1h, nullptr, b1, nullptr, nullptr, 0,
        h1h, nullptr, nullptr, nullptr, DIM, HID);
    // launch 3 — G2: h2 = tanh(h1 @ W2^T + b2); d2 = v3*(1-h2^2)
    mma_gemm<EPI_H2D2><<<dim3(HID / BN, BATCH / BM), THREADS, SMEM_TOTAL>>>(
        h1h, nullptr, w2h, nullptr, b2, v3p, nullptr, 0,
        h2h, d2h, nullptr, nullptr, HID, HID);
    // launch 4 — G34 merged: n<512: out = h2 @ W3^T + b3 (ldc=513)
    //                        n>=512: d1 = (d2 @ W2) * (1-h1^2)
    mma_gemm<EPI_G34><<<dim3((DIM + HID) / BN, BATCH / BM), THREADS, SMEM_TOTAL>>>(
        h2h, d2h, w3h, w2th, b3, nullptr, out, DIM + 1,
        d1h, nullptr, h1h, nullptr, HID, HID);
    // launch 5 — G5: g = d1 @ W1, trace fused in epilogue -> out[:,512]  <-- ncu -s 5
    mma_gemm<EPI_GT><<<dim3(DIM / BN, BATCH / BM), THREADS, SMEM_TOTAL>>>(
        d1h, nullptr, w1th, nullptr, nullptr, nullptr, out, DIM + 1,
        nullptr, nullptr, nullptr, eps, HID, 0);
}

// round 17
// speedup vs baseline: 1.0062x; 1.0062x over previous
#include <cuda_runtime.h>
#include <cuda_fp16.h>
#include <math.h>
#include <stdint.h>

#define BATCH 16384
#define DIM   512
#define HID   2048

#define BM 128
#define BN 128
#define BK 64
#define THREADS 128

// smem: 128B rows (64 fp16), XOR-swizzled 16B chunks (chunk ^= row&7)
#define OA_H   0
#define OB_H   16384
#define STAGE  32768
#define NSTAGE 3
#define SMEM_TOTAL (NSTAGE * STAGE)   // 98304/CTA -> 2 CTAs/SM

// ---------------- scratch (allocation-free) ----------------
__device__ __half g_zh[(size_t)BATCH * DIM];
__device__ __half g_h1h[(size_t)BATCH * HID];
__device__ __half g_h2h[(size_t)BATCH * HID];
__device__ __half g_d2h[(size_t)BATCH * HID];
__device__ __half g_d1h[(size_t)BATCH * HID];
__device__ float g_v3[HID];
__device__ __half g_W1h[HID * DIM];
__device__ __half g_W2h[HID * HID];
__device__ __half g_W3h[DIM * HID];
__device__ __half g_W2Th[HID * HID];
__device__ __half g_W1Th[DIM * HID];

enum { EPI_H1 = 0, EPI_H2D2 = 1, EPI_G34 = 2, EPI_GT = 3 };

// ---------------- helpers ----------------
__device__ __forceinline__ uint32_t s2u(const void* p) {
    uint32_t a;
    asm("{ .reg .u64 t; cvta.to.shared.u64 t, %1; cvt.u32.u64 %0, t; }" : "=r"(a) : "l"(p));
    return a;
}

// swizzled byte offset within a ROWSx64 fp16 tile: 128B rows, chunk ^= row&7
__device__ __forceinline__ uint32_t swoff(int row, int seg) {
    return (uint32_t)(row * 128 + ((seg ^ (row & 7)) << 4));
}

__device__ __forceinline__ void ldsm4(uint32_t* r, uint32_t addr) {
    asm volatile("ldmatrix.sync.aligned.m8n8.x4.shared.b16 {%0,%1,%2,%3}, [%4];"
                 : "=r"(r[0]), "=r"(r[1]), "=r"(r[2]), "=r"(r[3]) : "r"(addr));
}

__device__ __forceinline__ void mma16816(float* c, const uint32_t* a, const uint32_t* b) {
    asm volatile("mma.sync.aligned.m16n8k16.row.col.f32.f16.f16.f32 "
                 "{%0,%1,%2,%3}, {%4,%5,%6,%7}, {%8,%9}, {%0,%1,%2,%3};"
                 : "+f"(c[0]), "+f"(c[1]), "+f"(c[2]), "+f"(c[3])
                 : "r"(a[0]), "r"(a[1]), "r"(a[2]), "r"(a[3]), "r"(b[0]), "r"(b[1]));
}

__device__ __forceinline__ void cp16(uint32_t dst, const void* src) {
    asm volatile("cp.async.cg.shared.global [%0], [%1], 16;" :: "r"(dst), "l"(src) : "memory");
}

__device__ __forceinline__ float ftanh(float x) {
    float e = __expf(2.f * x);
    return 1.f - __fdividef(2.f, e + 1.f);
}

// one tile plane: 128 rows x 64 cols fp16 via cp.async into swizzled smem (128 threads)
__device__ __forceinline__ void cpPlane(uint32_t dst, const __half* __restrict__ src,
                                        int ld, int r0, int k0, int tid) {
#pragma unroll
    for (int i = 0; i < 8; ++i) {
        int idx = tid + i * 128;
        int row = idx >> 3, seg = idx & 7;
        cp16(dst + swoff(row, seg), src + (size_t)(r0 + row) * ld + k0 + seg * 8);
    }
}

// ---------------- fp16 warp-MMA GEMM: 128x128 tile, 4 warps of 64x64, BK=64, 3-stage ----------------
// acc = A[M,K_iter] * (B[N,K_iter])^T with leading dim ldk; EPI_GT splits K over gridDim.z
template <int EPI>
__global__ void __launch_bounds__(THREADS, 2) mma_gemm(
    const __half* __restrict__ Ah, const __half* __restrict__ A2,
    const __half* __restrict__ Bh, const __half* __restrict__ B2,
    const float* __restrict__ bias, const float* __restrict__ v3p,
    float* __restrict__ C, int ldc,
    __half* __restrict__ P1, __half* __restrict__ P2,
    const __half* __restrict__ Xh, const float* __restrict__ eps,
    int K, int ldp, int ldk)
{
    extern __shared__ char smem[];
    const uint32_t sb = s2u(smem);
    const int tid = threadIdx.x, lane = tid & 31, wid = tid >> 5;
    const int wm = wid >> 1, wn = wid & 1;           // 2x2 warps, 64x64 each
    const int m0 = blockIdx.y * BM, n0 = blockIdx.x * BN;
    const int NC = K >> 6;                            // 64-wide chunks

    // G34: n-tile selects operand set + epilogue flavor (uniform per CTA)
    bool isOut = true;
    int nB0 = n0;
    const __half* Ap = Ah;
    const __half* Bp = Bh;
    if (EPI == EPI_G34 && n0 >= DIM) {
        isOut = false; nB0 = n0 - DIM; Ap = A2; Bp = B2;
    }
    if (EPI == EPI_GT) {   // split-K: this CTA handles K-range [z*K, (z+1)*K)
        int kOff = blockIdx.z * K;
        Ap += kOff; Bp += kOff;
    }

    float acc[4][8][4];
#pragma unroll
    for (int a = 0; a < 4; ++a)
#pragma unroll
        for (int b = 0; b < 8; ++b)
#pragma unroll
            for (int c = 0; c < 4; ++c) acc[a][b][c] = 0.f;

    // swizzled fragment base offsets; ks step = XOR (ks<<5)
    const int aRow = lane & 15;
    const int bRow = (lane & 7) + ((lane >> 4) << 3);
    uint32_t aBase[4], bBase[4];
#pragma unroll
    for (int mb = 0; mb < 4; ++mb)
        aBase[mb] = swoff(wm * 64 + mb * 16 + aRow, lane >> 4);
#pragma unroll
    for (int pr = 0; pr < 4; ++pr)
        bBase[pr] = swoff(wn * 64 + pr * 16 + bRow, (lane >> 3) & 1);

    // prologue: chunks 0,1 -> stages 0,1
#pragma unroll
    for (int c = 0; c < 2; ++c) {
        const uint32_t st = sb + c * STAGE;
        if (c < NC) {
            cpPlane(st + OA_H, Ap, ldk, m0, c * BK, tid);
            cpPlane(st + OB_H, Bp, ldk, nB0, c * BK, tid);
        }
        asm volatile("cp.async.commit_group;" ::: "memory");
    }

    int sidx = 0;
    for (int c = 0; c < NC; ++c) {
        asm volatile("cp.async.wait_group 1;" ::: "memory");  // chunk c arrived
        __syncthreads();                                      // visibility + WAR (dist-2 write)
        if (c + 2 < NC) {
            int s2 = sidx + 2; if (s2 >= NSTAGE) s2 -= NSTAGE;
            const uint32_t nx = sb + s2 * STAGE;
            cpPlane(nx + OA_H, Ap, ldk, m0, (c + 2) * BK, tid);
            cpPlane(nx + OB_H, Bp, ldk, nB0, (c + 2) * BK, tid);
        }
        asm volatile("cp.async.commit_group;" ::: "memory");

        const uint32_t st = sb + sidx * STAGE;
#pragma unroll
        for (int ks = 0; ks < 4; ++ks) {
            const uint32_t kx = ks << 5;
            uint32_t bh[4][4], ah[4][4];
#pragma unroll
            for (int pr = 0; pr < 4; ++pr) ldsm4(bh[pr], st + OB_H + (bBase[pr] ^ kx));
#pragma unroll
            for (int mb = 0; mb < 4; ++mb) ldsm4(ah[mb], st + OA_H + (aBase[mb] ^ kx));
#pragma unroll
            for (int mb = 0; mb < 4; ++mb)
#pragma unroll
                for (int nb = 0; nb < 8; ++nb) {
                    const uint32_t* fh = &bh[nb >> 1][(nb & 1) * 2];
                    mma16816(acc[mb][nb], ah[mb], fh);
                }
        }
        if (++sidx == NSTAGE) sidx = 0;
    }

    // ---------------- epilogue ----------------
    const int g = lane >> 2, tg = lane & 3;
#pragma unroll
    for (int mb = 0; mb < 4; ++mb) {
        float p0 = 0.f, p1 = 0.f;   // EPI_GT per-row partial traces
#pragma unroll
        for (int nb = 0; nb < 8; ++nb) {
            float* cc = acc[mb][nb];
            const int r0 = m0 + wm * 64 + mb * 16 + g;
            const int col = nB0 + wn * 64 + nb * 8 + tg * 2;
            if (EPI == EPI_H1) {
                float bx = __ldg(bias + col), by = __ldg(bias + col + 1);
                float t0 = ftanh(cc[0] + bx), t1 = ftanh(cc[1] + by);
                float t2 = ftanh(cc[2] + bx), t3 = ftanh(cc[3] + by);
                *reinterpret_cast<__half2*>(P1 + (size_t)r0 * ldp + col) =
                    __halves2half2(__float2half_rn(t0), __float2half_rn(t1));
                *reinterpret_cast<__half2*>(P1 + (size_t)(r0 + 8) * ldp + col) =
                    __halves2half2(__float2half_rn(t2), __float2half_rn(t3));
            } else if (EPI == EPI_H2D2) {
                float bx = __ldg(bias + col), by = __ldg(bias + col + 1);
                float vx = __ldg(v3p + col), vy = __ldg(v3p + col + 1);
                float t0 = ftanh(cc[0] + bx), t1 = ftanh(cc[1] + by);
                float t2 = ftanh(cc[2] + bx), t3 = ftanh(cc[3] + by);
                *reinterpret_cast<__half2*>(P1 + (size_t)r0 * ldp + col) =
                    __halves2half2(__float2half_rn(t0), __float2half_rn(t1));
                *reinterpret_cast<__half2*>(P1 + (size_t)(r0 + 8) * ldp + col) =
                    __halves2half2(__float2half_rn(t2), __float2half_rn(t3));
                *reinterpret_cast<__half2*>(P2 + (size_t)r0 * ldp + col) =
                    __halves2half2(__float2half_rn(vx * (1.f - t0 * t0)),
                                   __float2half_rn(vy * (1.f - t1 * t1)));
                *reinterpret_cast<__half2*>(P2 + (size_t)(r0 + 8) * ldp + col) =
                    __halves2half2(__float2half_rn(vx * (1.f - t2 * t2)),
                                   __float2half_rn(vy * (1.f - t3 * t3)));
            } else if (EPI == EPI_G34) {
                if (isOut) {
                    float bx = __ldg(bias + col), by = __ldg(bias + col + 1);
                    C[(size_t)r0 * ldc + col]     = cc[0] + bx;
                    C[(size_t)r0 * ldc + col + 1] = cc[1] + by;
                    C[(size_t)(r0 + 8) * ldc + col]     = cc[2] + bx;
                    C[(size_t)(r0 + 8) * ldc + col + 1] = cc[3] + by;
                } else {
#pragma unroll
                    for (int rr = 0; rr < 2; ++rr) {
                        size_t off = (size_t)(r0 + rr * 8) * ldp + col;
                        __half2 hh = *reinterpret_cast<const __half2*>(Xh + off);
                        float h0 = __half2float(hh.x), h1 = __half2float(hh.y);
                        *reinterpret_cast<__half2*>(P1 + off) = __halves2half2(
                            __float2half_rn(cc[rr * 2] * (1.f - h0 * h0)),
                            __float2half_rn(cc[rr * 2 + 1] * (1.f - h1 * h1)));
                    }
                }
            } else {  // EPI_GT: partial g stays in regs; dot with 3 eps vectors
                size_t o0 = (size_t)r0 * DIM + col;
                size_t o1 = (size_t)(r0 + 8) * DIM + col;
                float2 a0 = *(const float2*)(eps + o0);
                float2 b0 = *(const float2*)(eps + (size_t)BATCH * DIM + o0);
                float2 c0 = *(const float2*)(eps + (size_t)2 * BATCH * DIM + o0);
                float2 a1 = *(const float2*)(eps + o1);
                float2 b1 = *(const float2*)(eps + (size_t)BATCH * DIM + o1);
                float2 c1 = *(const float2*)(eps + (size_t)2 * BATCH * DIM + o1);
                p0 += cc[0] * (a0.x + b0.x + c0.x) + cc[1] * (a0.y + b0.y + c0.y);
                p1 += cc[2] * (a1.x + b1.x + c1.x) + cc[3] * (a1.y + b1.y + c1.y);
            }
        }
        if (EPI == EPI_GT) {
            p0 += __shfl_xor_sync(0xFFFFFFFFu, p0, 1);
            p0 += __shfl_xor_sync(0xFFFFFFFFu, p0, 2);
            p1 += __shfl_xor_sync(0xFFFFFFFFu, p1, 1);
            p1 += __shfl_xor_sync(0xFFFFFFFFu, p1, 2);
            if (tg == 0) {
                const int r0 = m0 + wm * 64 + mb * 16 + g;
                atomicAdd(C + (size_t)r0 * (DIM + 1) + DIM, p0 * (1.f / 3.f));
                atomicAdd(C + (size_t)(r0 + 8) * (DIM + 1) + DIM, p1 * (1.f / 3.f));
            }
        }
    }
}

// ---------------- merged prep kernel (fused split + transpose) ----------------
// segments: W3 split (4096) | W1 fused split+T (1024) | W2 fused split+T (4096) | v3 (8)
#define PB_W3   4096
#define PB_W1T  (PB_W3 + 1024)
#define PB_W2T  (PB_W1T + 4096)
#define PB_V3   (PB_W2T + 8)

__device__ __forceinline__ void seg_split(const float* __restrict__ W,
                                          __half* __restrict__ hi,
                                          int base, int tid) {
    int i = base * 256 + tid;
    hi[i] = __float2half_rn(W[i]);
}

// read in[k][n] tile once; write hiN (same layout) and hiT (transposed) fp16
__device__ __forceinline__ void seg_splitT_fused(const float* __restrict__ in,
                                                 __half* __restrict__ hiN,
                                                 __half* __restrict__ hiT,
                                                 int K, int Nn, int tileIdx, int tid) {
    __shared__ float t[32][33];
    int tilesX = K / 32;
    int k0 = (tileIdx % tilesX) * 32, n0 = (tileIdx / tilesX) * 32;
    int tx = tid & 31, ty = tid >> 5;
#pragma unroll
    for (int i = 0; i < 32; i += 8) {
        float v = in[(size_t)(k0 + ty + i) * Nn + n0 + tx];
        t[ty + i][tx] = v;
        hiN[(size_t)(k0 + ty + i) * Nn + n0 + tx] = __float2half_rn(v);
    }
    __syncthreads();
#pragma unroll
    for (int i = 0; i < 32; i += 8)
        hiT[(size_t)(n0 + ty + i) * K + k0 + tx] = __float2half_rn(t[tx][ty + i]);
}

__global__ void __launch_bounds__(256) k_prep(const float* __restrict__ W1,
                                              const float* __restrict__ W2,
                                              const float* __restrict__ W3) {
    int b = blockIdx.x, tid = threadIdx.x;
    if (b < PB_W3) {
        seg_split(W3, g_W3h, b, tid);
    } else if (b < PB_W1T) {
        seg_splitT_fused(W1, g_W1h, g_W1Th, HID, DIM, b - PB_W3, tid);
    } else if (b < PB_W2T) {
        seg_splitT_fused(W2, g_W2h, g_W2Th, HID, HID, b - PB_W1T, tid);
    } else {
        int j = (b - PB_W2T) * 256 + tid;
        float s = 0.f;
#pragma unroll 8
        for (int i = 0; i < DIM; ++i) s += W3[(size_t)i * HID + j];
        g_v3[j] = s;
    }
}

// pack z to fp16 AND zero the trace column of out (re-done every replay)
__global__ void k_pack_z(const float* __restrict__ aug, float* __restrict__ out) {
    int b = blockIdx.x, t = threadIdx.x;
    g_zh[(size_t)b * DIM + t] = __float2half_rn(aug[(size_t)b * (DIM + 1) + t]);
    if (t == 0) out[(size_t)b * (DIM + 1) + DIM] = 0.f;
}

// ---------------- launch ----------------
extern "C" void kernel_launch(void* const* d_in, const int* in_sizes, int n_in,
                              void* d_out, int out_size) {
    const float* aug = (const float*)d_in[1];
    const float* eps = (const float*)d_in[2];
    const float* W1  = (const float*)d_in[3];
    const float* b1  = (const float*)d_in[4];
    const float* W2  = (const float*)d_in[5];
    const float* b2  = (const float*)d_in[6];
    const float* W3  = (const float*)d_in[7];
    const float* b3  = (const float*)d_in[8];
    float* out = (float*)d_out;

    __half *zh, *h1h, *h2h, *d2h, *d1h;
    cudaGetSymbolAddress((void**)&zh,  g_zh);
    cudaGetSymbolAddress((void**)&h1h, g_h1h);
    cudaGetSymbolAddress((void**)&h2h, g_h2h);
    cudaGetSymbolAddress((void**)&d2h, g_d2h);
    cudaGetSymbolAddress((void**)&d1h, g_d1h);
    float *v3p;
    cudaGetSymbolAddress((void**)&v3p, g_v3);
    __half *w1h, *w2h, *w3h, *w2th, *w1th;
    cudaGetSymbolAddress((void**)&w1h,  g_W1h);
    cudaGetSymbolAddress((void**)&w2h,  g_W2h);
    cudaGetSymbolAddress((void**)&w3h,  g_W3h);
    cudaGetSymbolAddress((void**)&w2th, g_W2Th);
    cudaGetSymbolAddress((void**)&w1th, g_W1Th);

    cudaFuncSetAttribute(mma_gemm<EPI_H1>,   cudaFuncAttributeMaxDynamicSharedMemorySize, SMEM_TOTAL);
    cudaFuncSetAttribute(mma_gemm<EPI_H2D2>, cudaFuncAttributeMaxDynamicSharedMemorySize, SMEM_TOTAL);
    cudaFuncSetAttribute(mma_gemm<EPI_G34>,  cudaFuncAttributeMaxDynamicSharedMemorySize, SMEM_TOTAL);
    cudaFuncSetAttribute(mma_gemm<EPI_GT>,   cudaFuncAttributeMaxDynamicSharedMemorySize, SMEM_TOTAL);

    // launch 0: all weight prep in one grid (fused split+transpose)
    k_prep<<<PB_V3, 256>>>(W1, W2, W3);
    // launch 1: activation pack + trace-column zero
    k_pack_z<<<BATCH, DIM>>>(aug, out);

    // launch 2 — G1: h1 = tanh(z @ W1^T + b1)   [K=512]
    mma_gemm<EPI_H1><<<dim3(HID / BN, BATCH / BM), THREADS, SMEM_TOTAL>>>(
        zh, nullptr, w1h, nullptr, b1, nullptr, nullptr, 0,
        h1h, nullptr, nullptr, nullptr, DIM, HID, DIM);
    // launch 3 — G2: h2 = tanh(h1 @ W2^T + b2); d2 = v3*(1-h2^2)
    mma_gemm<EPI_H2D2><<<dim3(HID / BN, BATCH / BM), THREADS, SMEM_TOTAL>>>(
        h1h, nullptr, w2h, nullptr, b2, v3p, nullptr, 0,
        h2h, d2h, nullptr, nullptr, HID, HID, HID);
    // launch 4 — G34 merged: n<512: out = h2 @ W3^T + b3 (ldc=513)
    //                        n>=512: d1 = (d2 @ W2) * (1-h1^2)
    mma_gemm<EPI_G34><<<dim3((DIM + HID) / BN, BATCH / BM), THREADS, SMEM_TOTAL>>>(
        h2h, d2h, w3h, w2th, b3, nullptr, out, DIM + 1,
        d1h, nullptr, h1h, nullptr, HID, HID, HID);
    // launch 5 — G5 split-K x2: trace += eps . (d1 @ W1 partial-K) -> out[:,512]
    mma_gemm<EPI_GT><<<dim3(DIM / BN, BATCH / BM, 2), THREADS, SMEM_TOTAL>>>(
        d1h, nullptr, w1th, nullptr, nullptr, nullptr, out, DIM + 1,
        nullptr, nullptr, nullptr, eps, HID / 2, 0, HID);
}